// round 7
// baseline (speedup 1.0000x reference)
#include <cuda_runtime.h>
#include <cuda_bf16.h>
#include <math.h>
#include <stdint.h>

// Problem constants
#define T_TOK 2048
#define H_DIM 1024
#define I_DIM 512
#define NE    16
#define TK    4
#define NPAIR (T_TOK * TK)   // 8192

// ---------------- scratch (device globals; no allocation) ----------------
__device__ int   g_offsets[NE + 1];
__device__ int   g_ids[NPAIR];
__device__ float g_wt[NPAIR];
__device__ int   g_slot[NPAIR];

__device__ __align__(16) __nv_bfloat16 g_xhi[T_TOK * H_DIM];
__device__ __align__(16) __nv_bfloat16 g_xlo[T_TOK * H_DIM];
__device__ __align__(16) __nv_bfloat16 g_wu_hi[NE * I_DIM * H_DIM];
__device__ __align__(16) __nv_bfloat16 g_wu_lo[NE * I_DIM * H_DIM];
__device__ __align__(16) __nv_bfloat16 g_wg_hi[NE * I_DIM * H_DIM];
__device__ __align__(16) __nv_bfloat16 g_wg_lo[NE * I_DIM * H_DIM];
__device__ __align__(16) __nv_bfloat16 g_wd_hi[NE * H_DIM * I_DIM];
__device__ __align__(16) __nv_bfloat16 g_wd_lo[NE * H_DIM * I_DIM];
__device__ __align__(16) __nv_bfloat16 g_hhi[(size_t)NPAIR * I_DIM];
__device__ __align__(16) __nv_bfloat16 g_hlo[(size_t)NPAIR * I_DIM];
__device__ __align__(16) float g_part[(size_t)NPAIR * H_DIM];   // 32 MB

// ---------------- helpers ----------------
__device__ __forceinline__ uint32_t smem_u32(const void* p) {
    uint32_t a;
    asm("{ .reg .u64 t; cvta.to.shared.u64 t, %1; cvt.u32.u64 %0, t; }" : "=r"(a) : "l"(p));
    return a;
}
__device__ __forceinline__ void cp_async16(uint32_t dst, const void* src) {
    asm volatile("cp.async.cg.shared.global [%0], [%1], 16;" :: "r"(dst), "l"(src));
}
__device__ __forceinline__ void ldmx4(uint32_t r[4], uint32_t addr) {
    asm volatile("ldmatrix.sync.aligned.m8n8.x4.shared.b16 {%0,%1,%2,%3}, [%4];"
                 : "=r"(r[0]), "=r"(r[1]), "=r"(r[2]), "=r"(r[3]) : "r"(addr));
}
__device__ __forceinline__ void mma16816(float d[4], const uint32_t a[4], uint32_t b0, uint32_t b1) {
    asm("mma.sync.aligned.m16n8k16.row.col.f32.bf16.bf16.f32 "
        "{%0,%1,%2,%3}, {%4,%5,%6,%7}, {%8,%9}, {%0,%1,%2,%3};"
        : "+f"(d[0]), "+f"(d[1]), "+f"(d[2]), "+f"(d[3])
        : "r"(a[0]), "r"(a[1]), "r"(a[2]), "r"(a[3]), "r"(b0), "r"(b1));
}
#define SWZ(o) ((o) ^ (((o) >> 3) & 0x70))

// ---------------- kernel: fused routing (router + scan + scatter), 1 block ----------------
__global__ void __launch_bounds__(1024) routing_kernel(const float* __restrict__ logits) {
    __shared__ int s_cnt[NE], s_cur[NE], s_off[NE + 1];
    int tid = threadIdx.x;
    if (tid < NE) { s_cnt[tid] = 0; s_cur[tid] = 0; }
    __syncthreads();

    for (int t = tid; t < T_TOK; t += 1024) {
        float l[NE];
#pragma unroll
        for (int e = 0; e < NE; e++) l[e] = logits[t * NE + e];
        int ids[TK]; float vals[TK];
        unsigned mask = 0;
#pragma unroll
        for (int k = 0; k < TK; k++) {
            float best = -1e30f; int bi = 0;
#pragma unroll
            for (int e = 0; e < NE; e++)
                if (!((mask >> e) & 1u) && l[e] > best) { best = l[e]; bi = e; }
            ids[k] = bi; vals[k] = best; mask |= (1u << bi);
        }
        float m = vals[0];
        float w[TK]; float s = 0.f;
#pragma unroll
        for (int k = 0; k < TK; k++) { w[k] = expf(vals[k] - m); s += w[k]; }
        float inv = 1.f / s;
#pragma unroll
        for (int k = 0; k < TK; k++) {
            g_ids[t * TK + k] = ids[k];
            g_wt[t * TK + k]  = w[k] * inv;
            atomicAdd(&s_cnt[ids[k]], 1);
        }
    }
    __syncthreads();
    if (tid == 0) {
        int acc = 0;
        s_off[0] = 0; g_offsets[0] = 0;
#pragma unroll
        for (int e = 0; e < NE; e++) {
            acc += s_cnt[e];
            s_off[e + 1] = acc;
            g_offsets[e + 1] = acc;
        }
    }
    __syncthreads();
    for (int t = tid; t < T_TOK; t += 1024) {
#pragma unroll
        for (int k = 0; k < TK; k++) {
            int e = g_ids[t * TK + k];
            int pos = s_off[e] + atomicAdd(&s_cur[e], 1);
            g_slot[pos] = t * TK + k;
        }
    }
}

// ---------------- tiny spacer so the profiler's 4th-launch slot = pass1 ----------------
__global__ void noop_kernel() {}

// ---------------- kernel: fused fp32 -> bf16 hi/lo split for all 4 tensors ----------------
#define NX4 (T_TOK * H_DIM / 4)
#define NW4 (NE * I_DIM * H_DIM / 4)
__global__ void conv_all_kernel(const float4* __restrict__ x,
                                const float4* __restrict__ wu,
                                const float4* __restrict__ wg,
                                const float4* __restrict__ wd) {
    int i = blockIdx.x * blockDim.x + threadIdx.x;
    const float4* src; __nv_bfloat16* hi; __nv_bfloat16* lo; int idx;
    if (i < NX4)                { src = x;  hi = g_xhi;  lo = g_xlo;  idx = i; }
    else if (i < NX4 + NW4)     { src = wu; hi = g_wu_hi; lo = g_wu_lo; idx = i - NX4; }
    else if (i < NX4 + 2 * NW4) { src = wg; hi = g_wg_hi; lo = g_wg_lo; idx = i - NX4 - NW4; }
    else if (i < NX4 + 3 * NW4) { src = wd; hi = g_wd_hi; lo = g_wd_lo; idx = i - NX4 - 2 * NW4; }
    else return;
    float4 v = src[idx];
    __nv_bfloat16 h0 = __float2bfloat16_rn(v.x);
    __nv_bfloat16 h1 = __float2bfloat16_rn(v.y);
    __nv_bfloat16 h2 = __float2bfloat16_rn(v.z);
    __nv_bfloat16 h3 = __float2bfloat16_rn(v.w);
    __nv_bfloat16 l0 = __float2bfloat16_rn(v.x - __bfloat162float(h0));
    __nv_bfloat16 l1 = __float2bfloat16_rn(v.y - __bfloat162float(h1));
    __nv_bfloat16 l2 = __float2bfloat16_rn(v.z - __bfloat162float(h2));
    __nv_bfloat16 l3 = __float2bfloat16_rn(v.w - __bfloat162float(h3));
    *(__nv_bfloat162*)&hi[4 * idx + 0] = __halves2bfloat162(h0, h1);
    *(__nv_bfloat162*)&hi[4 * idx + 2] = __halves2bfloat162(h2, h3);
    *(__nv_bfloat162*)&lo[4 * idx + 0] = __halves2bfloat162(l0, l1);
    *(__nv_bfloat162*)&lo[4 * idx + 2] = __halves2bfloat162(l2, l3);
}

// ============================================================================
// pass1: grouped HMMA GEMM, CTA 64x64, K=1024, fused up+gate, 3-term split
// 2-stage, dual-sync, 99KB smem -> 2 CTAs/SM; hoisted cp.async addressing
// ============================================================================
#define P1_ATILE 8192                           // 64 rows x 128B
#define P1_BTILE 8192                           // 64 rows x 128B
#define P1_STAGE (2 * P1_ATILE + 4 * P1_BTILE)  // 49152
#define P1_SMEM  (1024 + 2 * P1_STAGE)          // 99328 -> 2 CTAs/SM
#define P1_NC    16

__global__ void __launch_bounds__(256, 2) pass1_mma() {
    int e     = blockIdx.z;
    int mBase = g_offsets[e];
    int mEnd  = g_offsets[e + 1];
    int m0    = mBase + blockIdx.y * 64;
    if (m0 >= mEnd) return;
    int n0 = blockIdx.x * 64;

    extern __shared__ char smem[];
    int*   s_tok = (int*)smem;            // 64 ints
    float* s_wt  = (float*)(smem + 256);  // 64 floats
    uint32_t tb  = smem_u32(smem + 1024);

    int tid = threadIdx.x, wid = tid >> 5, lane = tid & 31;
    for (int r = tid; r < 64; r += 256) {
        int gm = m0 + r;
        int slot = (gm < mEnd) ? g_slot[gm] : g_slot[mBase];
        s_tok[r] = slot >> 2;
        s_wt[r]  = g_wt[slot];
    }
    __syncthreads();

    // ---- hoisted per-thread load state: row lrow, q-pair qp (q = qp, qp+1) ----
    int lrow = tid >> 2;            // 0..63
    int qp   = (tid & 3) * 2;       // 0,2,4,6
    uint32_t rbase = (uint32_t)lrow * 128;
    uint32_t cswz  = (rbase >> 3) & 0x70;
    uint32_t d0 = rbase + ((uint32_t)(qp * 16) ^ cswz);
    uint32_t d1 = rbase + ((uint32_t)(qp * 16 + 16) ^ cswz);
    size_t aoff = (size_t)s_tok[lrow] * H_DIM + qp * 8;
    size_t boff = ((size_t)e * I_DIM + n0 + lrow) * H_DIM + qp * 8;
    const __nv_bfloat16* sAh = g_xhi   + aoff;
    const __nv_bfloat16* sAl = g_xlo   + aoff;
    const __nv_bfloat16* sUh = g_wu_hi + boff;
    const __nv_bfloat16* sUl = g_wu_lo + boff;
    const __nv_bfloat16* sGh = g_wg_hi + boff;
    const __nv_bfloat16* sGl = g_wg_lo + boff;

    float accU[2][2][4], accG[2][2][4];
#pragma unroll
    for (int a = 0; a < 2; a++)
#pragma unroll
        for (int b = 0; b < 2; b++)
#pragma unroll
            for (int c = 0; c < 4; c++) { accU[a][b][c] = 0.f; accG[a][b][c] = 0.f; }

    int wm = (wid >> 2) * 32;     // warp m offset: 0 or 32
    int wn = (wid & 3) * 16;      // warp n offset: 0,16,32,48
    int lgrp = lane >> 3, lr = lane & 7;
    int rowA = wm + (lgrp & 1) * 8 + lr;
    int rowB = wn + (lgrp >> 1) * 8 + lr;

    // prologue: chunk 0 into stage 0
    {
        uint32_t sb_ = tb;
        cp_async16(sb_ + d0, sAh);                      cp_async16(sb_ + d1, sAh + 8);
        cp_async16(sb_ + P1_ATILE + d0, sAl);           cp_async16(sb_ + P1_ATILE + d1, sAl + 8);
        cp_async16(sb_ + 2 * P1_ATILE + d0, sUh);       cp_async16(sb_ + 2 * P1_ATILE + d1, sUh + 8);
        cp_async16(sb_ + 2 * P1_ATILE + P1_BTILE + d0, sUl);
        cp_async16(sb_ + 2 * P1_ATILE + P1_BTILE + d1, sUl + 8);
        cp_async16(sb_ + 2 * P1_ATILE + 2 * P1_BTILE + d0, sGh);
        cp_async16(sb_ + 2 * P1_ATILE + 2 * P1_BTILE + d1, sGh + 8);
        cp_async16(sb_ + 2 * P1_ATILE + 3 * P1_BTILE + d0, sGl);
        cp_async16(sb_ + 2 * P1_ATILE + 3 * P1_BTILE + d1, sGl + 8);
        asm volatile("cp.async.commit_group;" ::: "memory");
    }

    for (int c = 0; c < P1_NC; c++) {
        if (c + 1 < P1_NC) {
            int k0 = (c + 1) * 64;
            uint32_t sb_ = tb + ((c + 1) & 1) * P1_STAGE;
            cp_async16(sb_ + d0, sAh + k0);                 cp_async16(sb_ + d1, sAh + k0 + 8);
            cp_async16(sb_ + P1_ATILE + d0, sAl + k0);      cp_async16(sb_ + P1_ATILE + d1, sAl + k0 + 8);
            cp_async16(sb_ + 2 * P1_ATILE + d0, sUh + k0);  cp_async16(sb_ + 2 * P1_ATILE + d1, sUh + k0 + 8);
            cp_async16(sb_ + 2 * P1_ATILE + P1_BTILE + d0, sUl + k0);
            cp_async16(sb_ + 2 * P1_ATILE + P1_BTILE + d1, sUl + k0 + 8);
            cp_async16(sb_ + 2 * P1_ATILE + 2 * P1_BTILE + d0, sGh + k0);
            cp_async16(sb_ + 2 * P1_ATILE + 2 * P1_BTILE + d1, sGh + k0 + 8);
            cp_async16(sb_ + 2 * P1_ATILE + 3 * P1_BTILE + d0, sGl + k0);
            cp_async16(sb_ + 2 * P1_ATILE + 3 * P1_BTILE + d1, sGl + k0 + 8);
            asm volatile("cp.async.commit_group;" ::: "memory");
            asm volatile("cp.async.wait_group 1;" ::: "memory");
        } else {
            asm volatile("cp.async.wait_group 0;" ::: "memory");
        }
        __syncthreads();

        uint32_t st  = tb + (c & 1) * P1_STAGE;
        uint32_t aHi = st, aLo = st + P1_ATILE;
        uint32_t bU0 = st + 2 * P1_ATILE;            // up hi
        uint32_t bU1 = bU0 + P1_BTILE;               // up lo
        uint32_t bG0 = bU0 + 2 * P1_BTILE;           // gate hi
        uint32_t bG1 = bU0 + 3 * P1_BTILE;           // gate lo

#pragma unroll
        for (int s = 0; s < 4; s++) {
            int kaB = (s * 16 + (lgrp >> 1) * 8) * 2;   // A k byte offset
            int kbB = (s * 16 + (lgrp & 1) * 8) * 2;    // B k byte offset
            uint32_t Ah[2][4], Al[2][4];
            ldmx4(Ah[0], aHi + SWZ(rowA * 128 + kaB));
            ldmx4(Ah[1], aHi + SWZ((rowA + 16) * 128 + kaB));
            ldmx4(Al[0], aLo + SWZ(rowA * 128 + kaB));
            ldmx4(Al[1], aLo + SWZ((rowA + 16) * 128 + kaB));
            uint32_t Uh[4], Ul[4], Gh[4], Gl[4];
            {
                uint32_t off = SWZ(rowB * 128 + kbB);
                ldmx4(Uh, bU0 + off);
                ldmx4(Ul, bU1 + off);
                ldmx4(Gh, bG0 + off);
                ldmx4(Gl, bG1 + off);
            }
            // term-major: independent MMAs between accumulator reuses
#pragma unroll
            for (int mi = 0; mi < 2; mi++)
#pragma unroll
                for (int nf = 0; nf < 2; nf++) {
                    mma16816(accU[mi][nf], Ah[mi], Uh[nf * 2], Uh[nf * 2 + 1]);
                    mma16816(accG[mi][nf], Ah[mi], Gh[nf * 2], Gh[nf * 2 + 1]);
                }
#pragma unroll
            for (int mi = 0; mi < 2; mi++)
#pragma unroll
                for (int nf = 0; nf < 2; nf++) {
                    mma16816(accU[mi][nf], Al[mi], Uh[nf * 2], Uh[nf * 2 + 1]);
                    mma16816(accG[mi][nf], Al[mi], Gh[nf * 2], Gh[nf * 2 + 1]);
                }
#pragma unroll
            for (int mi = 0; mi < 2; mi++)
#pragma unroll
                for (int nf = 0; nf < 2; nf++) {
                    mma16816(accU[mi][nf], Ah[mi], Ul[nf * 2], Ul[nf * 2 + 1]);
                    mma16816(accG[mi][nf], Ah[mi], Gl[nf * 2], Gl[nf * 2 + 1]);
                }
        }
        __syncthreads();
    }

    // ---- epilogue: h = w * silu(w*g) * (w*u), re-split into bf16 hi/lo ----
    int r4 = lane >> 2, c2 = (lane & 3) * 2;
#pragma unroll
    for (int mi = 0; mi < 2; mi++) {
#pragma unroll
        for (int half = 0; half < 2; half++) {
            int row = wm + mi * 16 + half * 8 + r4;
            int gm  = m0 + row;
            if (gm >= mEnd) continue;
            float w = s_wt[row];
#pragma unroll
            for (int nf = 0; nf < 2; nf++) {
                int col = n0 + wn + nf * 8 + c2;
                float u0 = w * accU[mi][nf][half * 2 + 0];
                float u1 = w * accU[mi][nf][half * 2 + 1];
                float gg0 = w * accG[mi][nf][half * 2 + 0];
                float gg1 = w * accG[mi][nf][half * 2 + 1];
                float r0 = w * (gg0 / (1.f + __expf(-gg0))) * u0;
                float r1 = w * (gg1 / (1.f + __expf(-gg1))) * u1;
                __nv_bfloat16 h0 = __float2bfloat16_rn(r0);
                __nv_bfloat16 h1 = __float2bfloat16_rn(r1);
                __nv_bfloat16 l0 = __float2bfloat16_rn(r0 - __bfloat162float(h0));
                __nv_bfloat16 l1 = __float2bfloat16_rn(r1 - __bfloat162float(h1));
                *(__nv_bfloat162*)&g_hhi[(size_t)gm * I_DIM + col] = __halves2bfloat162(h0, h1);
                *(__nv_bfloat162*)&g_hlo[(size_t)gm * I_DIM + col] = __halves2bfloat162(l0, l1);
            }
        }
    }
}

// ============================================================================
// pass2: grouped HMMA GEMM h @ w_down^T, CTA 128x64, K=512, 3-term split
// 2-stage, dual-sync, 99KB smem -> 2 CTAs/SM; hoisted cp.async addressing
// ============================================================================
#define P2_ATILE 16384
#define P2_BTILE 8192
#define P2_STAGE (2 * P2_ATILE + 2 * P2_BTILE)  // 49152
#define P2_SMEM  (1024 + 2 * P2_STAGE)          // 99328
#define P2_NC    8

__global__ void __launch_bounds__(256, 2) pass2_mma() {
    int e     = blockIdx.z;
    int mBase = g_offsets[e];
    int mEnd  = g_offsets[e + 1];
    int m0    = mBase + blockIdx.y * 128;
    if (m0 >= mEnd) return;
    int n0 = blockIdx.x * 64;

    extern __shared__ char smem[];
    int* s_row  = (int*)smem;
    int* s_slot = (int*)(smem + 512);
    uint32_t tb = smem_u32(smem + 1024);

    int tid = threadIdx.x, wid = tid >> 5, lane = tid & 31;
    for (int r = tid; r < 128; r += 256) {
        int gm = m0 + r;
        s_row[r]  = (gm < mEnd) ? gm : mBase;
        s_slot[r] = (gm < mEnd) ? g_slot[gm] : 0;
    }
    __syncthreads();

    // ---- hoisted load state ----
    // A: 128 rows x 8 q; thread: rowA2 = tid>>1 (0..127), qa = (tid&1)*4 .. +3
    int rowA2 = tid >> 1;
    int qa    = (tid & 1) * 4;
    uint32_t rbA = (uint32_t)rowA2 * 128;
    uint32_t cA  = (rbA >> 3) & 0x70;
    uint32_t dA[4];
#pragma unroll
    for (int j = 0; j < 4; j++) dA[j] = rbA + (((uint32_t)(qa + j) * 16) ^ cA);
    size_t aoff = (size_t)s_row[rowA2] * I_DIM + qa * 8;
    const __nv_bfloat16* sAh = g_hhi + aoff;
    const __nv_bfloat16* sAl = g_hlo + aoff;
    // B: 64 rows x 8 q; thread: rowB2 = tid>>2 (0..63), qb = (tid&3)*2 .. +1
    int rowB2 = tid >> 2;
    int qb    = (tid & 3) * 2;
    uint32_t rbB = (uint32_t)rowB2 * 128;
    uint32_t cB  = (rbB >> 3) & 0x70;
    uint32_t dB0 = rbB + (((uint32_t)qb * 16) ^ cB);
    uint32_t dB1 = rbB + (((uint32_t)(qb * 16 + 16)) ^ cB);
    size_t boff = ((size_t)e * H_DIM + n0 + rowB2) * I_DIM + qb * 8;
    const __nv_bfloat16* sBh = g_wd_hi + boff;
    const __nv_bfloat16* sBl = g_wd_lo + boff;

    float acc[2][4][4];
#pragma unroll
    for (int a = 0; a < 2; a++)
#pragma unroll
        for (int b = 0; b < 4; b++)
#pragma unroll
            for (int c = 0; c < 4; c++) acc[a][b][c] = 0.f;

    int wm = (wid >> 1) * 32;
    int wn = (wid & 1) * 32;
    int lgrp = lane >> 3, lr = lane & 7;
    int rowA = wm + (lgrp & 1) * 8 + lr;
    int rowB = wn + (lgrp >> 1) * 8 + lr;

    {
        uint32_t sb_ = tb;
#pragma unroll
        for (int j = 0; j < 4; j++) {
            cp_async16(sb_ + dA[j], sAh + j * 8);
            cp_async16(sb_ + P2_ATILE + dA[j], sAl + j * 8);
        }
        cp_async16(sb_ + 2 * P2_ATILE + dB0, sBh);
        cp_async16(sb_ + 2 * P2_ATILE + dB1, sBh + 8);
        cp_async16(sb_ + 2 * P2_ATILE + P2_BTILE + dB0, sBl);
        cp_async16(sb_ + 2 * P2_ATILE + P2_BTILE + dB1, sBl + 8);
        asm volatile("cp.async.commit_group;" ::: "memory");
    }

    for (int c = 0; c < P2_NC; c++) {
        if (c + 1 < P2_NC) {
            int k0 = (c + 1) * 64;
            uint32_t sb_ = tb + ((c + 1) & 1) * P2_STAGE;
#pragma unroll
            for (int j = 0; j < 4; j++) {
                cp_async16(sb_ + dA[j], sAh + k0 + j * 8);
                cp_async16(sb_ + P2_ATILE + dA[j], sAl + k0 + j * 8);
            }
            cp_async16(sb_ + 2 * P2_ATILE + dB0, sBh + k0);
            cp_async16(sb_ + 2 * P2_ATILE + dB1, sBh + k0 + 8);
            cp_async16(sb_ + 2 * P2_ATILE + P2_BTILE + dB0, sBl + k0);
            cp_async16(sb_ + 2 * P2_ATILE + P2_BTILE + dB1, sBl + k0 + 8);
            asm volatile("cp.async.commit_group;" ::: "memory");
            asm volatile("cp.async.wait_group 1;" ::: "memory");
        } else {
            asm volatile("cp.async.wait_group 0;" ::: "memory");
        }
        __syncthreads();

        uint32_t st  = tb + (c & 1) * P2_STAGE;
        uint32_t aHi = st, aLo = st + P2_ATILE;
        uint32_t bHi = st + 2 * P2_ATILE, bLo = bHi + P2_BTILE;

#pragma unroll
        for (int s = 0; s < 4; s++) {
            int kaB = (s * 16 + (lgrp >> 1) * 8) * 2;
            int kbB = (s * 16 + (lgrp & 1) * 8) * 2;
            uint32_t Ah[2][4], Al[2][4];
            ldmx4(Ah[0], aHi + SWZ(rowA * 128 + kaB));
            ldmx4(Ah[1], aHi + SWZ((rowA + 16) * 128 + kaB));
            ldmx4(Al[0], aLo + SWZ(rowA * 128 + kaB));
            ldmx4(Al[1], aLo + SWZ((rowA + 16) * 128 + kaB));
            uint32_t Bh[2][4], Bl[2][4];
#pragma unroll
            for (int p = 0; p < 2; p++) {
                uint32_t off = SWZ((rowB + p * 16) * 128 + kbB);
                ldmx4(Bh[p], bHi + off);
                ldmx4(Bl[p], bLo + off);
            }
#pragma unroll
            for (int mi = 0; mi < 2; mi++)
#pragma unroll
                for (int nf = 0; nf < 4; nf++) {
                    int p = nf >> 1, h = (nf & 1) * 2;
                    mma16816(acc[mi][nf], Ah[mi], Bh[p][h], Bh[p][h + 1]);
                }
#pragma unroll
            for (int mi = 0; mi < 2; mi++)
#pragma unroll
                for (int nf = 0; nf < 4; nf++) {
                    int p = nf >> 1, h = (nf & 1) * 2;
                    mma16816(acc[mi][nf], Al[mi], Bh[p][h], Bh[p][h + 1]);
                }
#pragma unroll
            for (int mi = 0; mi < 2; mi++)
#pragma unroll
                for (int nf = 0; nf < 4; nf++) {
                    int p = nf >> 1, h = (nf & 1) * 2;
                    mma16816(acc[mi][nf], Ah[mi], Bl[p][h], Bl[p][h + 1]);
                }
        }
        __syncthreads();
    }

    int r4 = lane >> 2, c2 = (lane & 3) * 2;
#pragma unroll
    for (int mi = 0; mi < 2; mi++) {
#pragma unroll
        for (int half = 0; half < 2; half++) {
            int row = wm + mi * 16 + half * 8 + r4;
            int gm  = m0 + row;
            if (gm >= mEnd) continue;
            int slot = s_slot[row];
#pragma unroll
            for (int nf = 0; nf < 4; nf++) {
                int col = n0 + wn + nf * 8 + c2;
                float2 v = make_float2(acc[mi][nf][half * 2 + 0], acc[mi][nf][half * 2 + 1]);
                *(float2*)&g_part[(size_t)slot * H_DIM + col] = v;
            }
        }
    }
}

// ---------------- reduce ----------------
__global__ void reduce_kernel(float* __restrict__ out) {
    int i = blockIdx.x * blockDim.x + threadIdx.x;
    int total = T_TOK * H_DIM / 4;
    if (i >= total) return;
    int t  = i / (H_DIM / 4);
    int hc = (i % (H_DIM / 4)) * 4;
    float4 s = make_float4(0.f, 0.f, 0.f, 0.f);
#pragma unroll
    for (int k = 0; k < TK; k++) {
        float4 v = *(const float4*)&g_part[(size_t)(t * TK + k) * H_DIM + hc];
        s.x += v.x; s.y += v.y; s.z += v.z; s.w += v.w;
    }
    *(float4*)&out[(size_t)t * H_DIM + hc] = s;
}

// ---------------- launch ----------------
extern "C" void kernel_launch(void* const* d_in, const int* in_sizes, int n_in,
                              void* d_out, int out_size)
{
    const float* x             = (const float*)d_in[0];
    const float* router_logits = (const float*)d_in[1];
    const float* w_up          = (const float*)d_in[2];
    const float* w_gate        = (const float*)d_in[3];
    const float* w_down        = (const float*)d_in[4];
    float* out = (float*)d_out;

    cudaFuncSetAttribute(pass1_mma, cudaFuncAttributeMaxDynamicSharedMemorySize, P1_SMEM);
    cudaFuncSetAttribute(pass2_mma, cudaFuncAttributeMaxDynamicSharedMemorySize, P2_SMEM);

    // #1 routing, #2 conversions, #3 spacer, #4 pass1 (profiled), #5 pass2, #6 reduce
    routing_kernel<<<1, 1024>>>(router_logits);

    int ntot = NX4 + 3 * NW4;
    conv_all_kernel<<<(ntot + 255) / 256, 256>>>(
        (const float4*)x, (const float4*)w_up, (const float4*)w_gate, (const float4*)w_down);

    noop_kernel<<<1, 32>>>();

    dim3 g1(I_DIM / 64, T_TOK / 64, NE);
    pass1_mma<<<g1, 256, P1_SMEM>>>();

    dim3 g2(H_DIM / 64, T_TOK / 128, NE);
    pass2_mma<<<g2, 256, P2_SMEM>>>();

    reduce_kernel<<<(T_TOK * H_DIM / 4 + 255) / 256, 256>>>(out);
}

// round 9
// speedup vs baseline: 1.3302x; 1.3302x over previous
#include <cuda_runtime.h>
#include <cuda_bf16.h>
#include <math.h>
#include <stdint.h>

// Problem constants
#define T_TOK 2048
#define H_DIM 1024
#define I_DIM 512
#define NE    16
#define TK    4
#define NPAIR (T_TOK * TK)   // 8192

// ---------------- scratch (device globals; no allocation) ----------------
__device__ int   g_offsets[NE + 1];
__device__ int   g_ids[NPAIR];
__device__ float g_wt[NPAIR];
__device__ int   g_slot[NPAIR];

// int8 two-level quantized pass1 inputs + per-row scales
__device__ __align__(16) signed char g_x1[T_TOK * H_DIM];
__device__ __align__(16) signed char g_x2[T_TOK * H_DIM];
__device__ __align__(16) signed char g_u1[NE * I_DIM * H_DIM];
__device__ __align__(16) signed char g_u2[NE * I_DIM * H_DIM];
__device__ __align__(16) signed char g_g1[NE * I_DIM * H_DIM];
__device__ __align__(16) signed char g_g2[NE * I_DIM * H_DIM];
__device__ float g_sx[T_TOK];
__device__ float g_su[NE * I_DIM];
__device__ float g_sg[NE * I_DIM];

// bf16 hi/lo for pass2 (w_down and h)
__device__ __align__(16) __nv_bfloat16 g_wd_hi[NE * H_DIM * I_DIM];
__device__ __align__(16) __nv_bfloat16 g_wd_lo[NE * H_DIM * I_DIM];
__device__ __align__(16) __nv_bfloat16 g_hhi[(size_t)NPAIR * I_DIM];
__device__ __align__(16) __nv_bfloat16 g_hlo[(size_t)NPAIR * I_DIM];
__device__ __align__(16) float g_part[(size_t)NPAIR * H_DIM];   // 32 MB

// ---------------- helpers ----------------
__device__ __forceinline__ uint32_t smem_u32(const void* p) {
    uint32_t a;
    asm("{ .reg .u64 t; cvta.to.shared.u64 t, %1; cvt.u32.u64 %0, t; }" : "=r"(a) : "l"(p));
    return a;
}
__device__ __forceinline__ void cp_async16(uint32_t dst, const void* src) {
    asm volatile("cp.async.cg.shared.global [%0], [%1], 16;" :: "r"(dst), "l"(src));
}
__device__ __forceinline__ void ldmx4(uint32_t r[4], uint32_t addr) {
    asm volatile("ldmatrix.sync.aligned.m8n8.x4.shared.b16 {%0,%1,%2,%3}, [%4];"
                 : "=r"(r[0]), "=r"(r[1]), "=r"(r[2]), "=r"(r[3]) : "r"(addr));
}
__device__ __forceinline__ void mma16816(float d[4], const uint32_t a[4], uint32_t b0, uint32_t b1) {
    asm("mma.sync.aligned.m16n8k16.row.col.f32.bf16.bf16.f32 "
        "{%0,%1,%2,%3}, {%4,%5,%6,%7}, {%8,%9}, {%0,%1,%2,%3};"
        : "+f"(d[0]), "+f"(d[1]), "+f"(d[2]), "+f"(d[3])
        : "r"(a[0]), "r"(a[1]), "r"(a[2]), "r"(a[3]), "r"(b0), "r"(b1));
}
__device__ __forceinline__ void imma16832(int d[4], const uint32_t a[4], uint32_t b0, uint32_t b1) {
    asm("mma.sync.aligned.m16n8k32.row.col.s32.s8.s8.s32 "
        "{%0,%1,%2,%3}, {%4,%5,%6,%7}, {%8,%9}, {%0,%1,%2,%3};"
        : "+r"(d[0]), "+r"(d[1]), "+r"(d[2]), "+r"(d[3])
        : "r"(a[0]), "r"(a[1]), "r"(a[2]), "r"(a[3]), "r"(b0), "r"(b1));
}
#define SWZ(o) ((o) ^ (((o) >> 3) & 0x70))

// ---------------- kernel: fused routing (router + scan + scatter), 1 block ----------------
__global__ void __launch_bounds__(1024) routing_kernel(const float* __restrict__ logits) {
    __shared__ int s_cnt[NE], s_cur[NE], s_off[NE + 1];
    int tid = threadIdx.x;
    if (tid < NE) { s_cnt[tid] = 0; s_cur[tid] = 0; }
    __syncthreads();

    for (int t = tid; t < T_TOK; t += 1024) {
        float l[NE];
#pragma unroll
        for (int e = 0; e < NE; e++) l[e] = logits[t * NE + e];
        int ids[TK]; float vals[TK];
        unsigned mask = 0;
#pragma unroll
        for (int k = 0; k < TK; k++) {
            float best = -1e30f; int bi = 0;
#pragma unroll
            for (int e = 0; e < NE; e++)
                if (!((mask >> e) & 1u) && l[e] > best) { best = l[e]; bi = e; }
            ids[k] = bi; vals[k] = best; mask |= (1u << bi);
        }
        float m = vals[0];
        float w[TK]; float s = 0.f;
#pragma unroll
        for (int k = 0; k < TK; k++) { w[k] = expf(vals[k] - m); s += w[k]; }
        float inv = 1.f / s;
#pragma unroll
        for (int k = 0; k < TK; k++) {
            g_ids[t * TK + k] = ids[k];
            g_wt[t * TK + k]  = w[k] * inv;
            atomicAdd(&s_cnt[ids[k]], 1);
        }
    }
    __syncthreads();
    if (tid == 0) {
        int acc = 0;
        s_off[0] = 0; g_offsets[0] = 0;
#pragma unroll
        for (int e = 0; e < NE; e++) {
            acc += s_cnt[e];
            s_off[e + 1] = acc;
            g_offsets[e + 1] = acc;
        }
    }
    __syncthreads();
    for (int t = tid; t < T_TOK; t += 1024) {
#pragma unroll
        for (int k = 0; k < TK; k++) {
            int e = g_ids[t * TK + k];
            int pos = s_off[e] + atomicAdd(&s_cur[e], 1);
            g_slot[pos] = t * TK + k;
        }
    }
}

// ---------------- kernel: fp32 -> two-level int8 with per-row scale ----------------
// One block per row (row length H_DIM=1024, 128 threads x 8 elems).
// rows: [0,2048) -> x; [2048,10240) -> w_up; [10240,18432) -> w_gate
#define CONV8_ROWS (T_TOK + 2 * NE * I_DIM)
__global__ void __launch_bounds__(128) conv_int8_kernel(const float* __restrict__ x,
                                                        const float* __restrict__ wu,
                                                        const float* __restrict__ wg) {
    int r = blockIdx.x;
    const float* src; signed char* q1; signed char* q2; float* sc; int row;
    if (r < T_TOK)                 { src = x;  q1 = g_x1; q2 = g_x2; sc = g_sx; row = r; }
    else if (r < T_TOK + NE*I_DIM) { src = wu; q1 = g_u1; q2 = g_u2; sc = g_su; row = r - T_TOK; }
    else                           { src = wg; q1 = g_g1; q2 = g_g2; sc = g_sg; row = r - T_TOK - NE*I_DIM; }

    const float4* p4 = (const float4*)(src + (size_t)row * H_DIM + threadIdx.x * 8);
    float4 a = p4[0], b = p4[1];
    float v[8] = {a.x, a.y, a.z, a.w, b.x, b.y, b.z, b.w};
    float m = 0.f;
#pragma unroll
    for (int j = 0; j < 8; j++) m = fmaxf(m, fabsf(v[j]));
#pragma unroll
    for (int o = 16; o; o >>= 1) m = fmaxf(m, __shfl_xor_sync(0xFFFFFFFFu, m, o));
    __shared__ float sm[4];
    __shared__ float s_inv;
    if ((threadIdx.x & 31) == 0) sm[threadIdx.x >> 5] = m;
    __syncthreads();
    if (threadIdx.x == 0) {
        float mm = fmaxf(fmaxf(sm[0], sm[1]), fmaxf(sm[2], sm[3]));
        sc[row] = mm * (1.f / 127.f);
        s_inv   = (mm > 0.f) ? (127.f / mm) : 0.f;
    }
    __syncthreads();
    float inv = s_inv;
    unsigned long long u1 = 0, u2 = 0;
#pragma unroll
    for (int j = 0; j < 8; j++) {
        float t  = v[j] * inv;
        float t1 = rintf(t);
        int c1 = (int)t1;
        int c2 = (int)rintf((t - t1) * 128.f);
        u1 |= ((unsigned long long)(unsigned char)(signed char)c1) << (8 * j);
        u2 |= ((unsigned long long)(unsigned char)(signed char)c2) << (8 * j);
    }
    size_t o = (size_t)row * H_DIM + threadIdx.x * 8;
    *(unsigned long long*)(q1 + o) = u1;
    *(unsigned long long*)(q2 + o) = u2;
}

// ---------------- kernel: fp32 -> bf16 hi/lo for w_down only ----------------
#define NWD4 (NE * H_DIM * I_DIM / 4)
__global__ void conv_wd_kernel(const float4* __restrict__ wd) {
    int i = blockIdx.x * blockDim.x + threadIdx.x;
    if (i >= NWD4) return;
    float4 v = wd[i];
    __nv_bfloat16 h0 = __float2bfloat16_rn(v.x);
    __nv_bfloat16 h1 = __float2bfloat16_rn(v.y);
    __nv_bfloat16 h2 = __float2bfloat16_rn(v.z);
    __nv_bfloat16 h3 = __float2bfloat16_rn(v.w);
    __nv_bfloat16 l0 = __float2bfloat16_rn(v.x - __bfloat162float(h0));
    __nv_bfloat16 l1 = __float2bfloat16_rn(v.y - __bfloat162float(h1));
    __nv_bfloat16 l2 = __float2bfloat16_rn(v.z - __bfloat162float(h2));
    __nv_bfloat16 l3 = __float2bfloat16_rn(v.w - __bfloat162float(h3));
    *(__nv_bfloat162*)&g_wd_hi[4 * i + 0] = __halves2bfloat162(h0, h1);
    *(__nv_bfloat162*)&g_wd_hi[4 * i + 2] = __halves2bfloat162(h2, h3);
    *(__nv_bfloat162*)&g_wd_lo[4 * i + 0] = __halves2bfloat162(l0, l1);
    *(__nv_bfloat162*)&g_wd_lo[4 * i + 2] = __halves2bfloat162(l2, l3);
}

// ============================================================================
// pass1: grouped int8 IMMA GEMM, CTA 64x64, K=1024, fused up+gate,
// two-level int8 (3-term). Chunk = 128 int8 = 128B rows; same SW128 machinery.
// 2-stage, 2 CTAs/SM.
// ============================================================================
#define P1_TILE  8192                           // 64 rows x 128B
#define P1_STAGE (6 * P1_TILE)                  // A1,A2,U1,U2,G1,G2 = 48KB
#define P1_SMEM  (2048 + 2 * P1_STAGE)          // 100352 -> 2 CTAs/SM
#define P1_NC    8                              // 1024 / 128

__global__ void __launch_bounds__(256, 2) pass1_mma() {
    int e     = blockIdx.z;
    int mBase = g_offsets[e];
    int mEnd  = g_offsets[e + 1];
    int m0    = mBase + blockIdx.y * 64;
    if (m0 >= mEnd) return;
    int n0 = blockIdx.x * 64;

    extern __shared__ char smem[];
    int*   s_tok = (int*)smem;             // 64
    float* s_wt  = (float*)(smem + 256);   // 64
    float* s_sa  = (float*)(smem + 512);   // 64  A row scales
    float* s_su  = (float*)(smem + 768);   // 64  up col scales
    float* s_sg  = (float*)(smem + 1024);  // 64  gate col scales
    uint32_t tb  = smem_u32(smem + 2048);

    int tid = threadIdx.x, wid = tid >> 5, lane = tid & 31;
    for (int r = tid; r < 64; r += 256) {
        int gm = m0 + r;
        int slot = (gm < mEnd) ? g_slot[gm] : g_slot[mBase];
        int tok = slot >> 2;
        s_tok[r] = tok;
        s_wt[r]  = g_wt[slot];
        s_sa[r]  = g_sx[tok];
        s_su[r]  = g_su[e * I_DIM + n0 + r];
        s_sg[r]  = g_sg[e * I_DIM + n0 + r];
    }
    __syncthreads();

    // ---- hoisted per-thread load state: row lrow, 32B slice qp ----
    int lrow = tid >> 2;            // 0..63
    int qp   = tid & 3;             // 0..3 -> bytes qp*32 .. +31
    uint32_t rbase = (uint32_t)lrow * 128;
    uint32_t cswz  = (rbase >> 3) & 0x70;
    uint32_t d0 = rbase + (((uint32_t)(qp * 32)) ^ cswz);
    uint32_t d1 = rbase + (((uint32_t)(qp * 32 + 16)) ^ cswz);
    size_t aoff = (size_t)s_tok[lrow] * H_DIM + qp * 32;
    size_t boff = ((size_t)e * I_DIM + n0 + lrow) * H_DIM + qp * 32;
    const signed char* sA1 = g_x1 + aoff;
    const signed char* sA2 = g_x2 + aoff;
    const signed char* sU1 = g_u1 + boff;
    const signed char* sU2 = g_u2 + boff;
    const signed char* sG1 = g_g1 + boff;
    const signed char* sG2 = g_g2 + boff;

    int dU1[2][2][4], dU2[2][2][4], dG1[2][2][4], dG2[2][2][4];
#pragma unroll
    for (int a = 0; a < 2; a++)
#pragma unroll
        for (int b = 0; b < 2; b++)
#pragma unroll
            for (int c = 0; c < 4; c++) {
                dU1[a][b][c] = 0; dU2[a][b][c] = 0;
                dG1[a][b][c] = 0; dG2[a][b][c] = 0;
            }

    int wm = (wid >> 2) * 32;     // warp m offset: 0 or 32
    int wn = (wid & 3) * 16;      // warp n offset: 0,16,32,48
    int lgrp = lane >> 3, lr = lane & 7;
    int rowA = wm + (lgrp & 1) * 8 + lr;
    int rowB = wn + (lgrp >> 1) * 8 + lr;
    int colA = (lgrp >> 1) * 16;  // A: col by lgrp>>1
    int colB = (lgrp & 1) * 16;   // B: col by lgrp&1

    // prologue: chunk 0 into stage 0
    {
        uint32_t sb_ = tb;
        cp_async16(sb_ + d0, sA1);                   cp_async16(sb_ + d1, sA1 + 16);
        cp_async16(sb_ + P1_TILE + d0, sA2);         cp_async16(sb_ + P1_TILE + d1, sA2 + 16);
        cp_async16(sb_ + 2 * P1_TILE + d0, sU1);     cp_async16(sb_ + 2 * P1_TILE + d1, sU1 + 16);
        cp_async16(sb_ + 3 * P1_TILE + d0, sU2);     cp_async16(sb_ + 3 * P1_TILE + d1, sU2 + 16);
        cp_async16(sb_ + 4 * P1_TILE + d0, sG1);     cp_async16(sb_ + 4 * P1_TILE + d1, sG1 + 16);
        cp_async16(sb_ + 5 * P1_TILE + d0, sG2);     cp_async16(sb_ + 5 * P1_TILE + d1, sG2 + 16);
        asm volatile("cp.async.commit_group;" ::: "memory");
    }

    for (int c = 0; c < P1_NC; c++) {
        if (c + 1 < P1_NC) {
            int k0 = (c + 1) * 128;
            uint32_t sb_ = tb + ((c + 1) & 1) * P1_STAGE;
            cp_async16(sb_ + d0, sA1 + k0);                cp_async16(sb_ + d1, sA1 + k0 + 16);
            cp_async16(sb_ + P1_TILE + d0, sA2 + k0);      cp_async16(sb_ + P1_TILE + d1, sA2 + k0 + 16);
            cp_async16(sb_ + 2 * P1_TILE + d0, sU1 + k0);  cp_async16(sb_ + 2 * P1_TILE + d1, sU1 + k0 + 16);
            cp_async16(sb_ + 3 * P1_TILE + d0, sU2 + k0);  cp_async16(sb_ + 3 * P1_TILE + d1, sU2 + k0 + 16);
            cp_async16(sb_ + 4 * P1_TILE + d0, sG1 + k0);  cp_async16(sb_ + 4 * P1_TILE + d1, sG1 + k0 + 16);
            cp_async16(sb_ + 5 * P1_TILE + d0, sG2 + k0);  cp_async16(sb_ + 5 * P1_TILE + d1, sG2 + k0 + 16);
            asm volatile("cp.async.commit_group;" ::: "memory");
            asm volatile("cp.async.wait_group 1;" ::: "memory");
        } else {
            asm volatile("cp.async.wait_group 0;" ::: "memory");
        }
        __syncthreads();

        uint32_t st = tb + (c & 1) * P1_STAGE;
        uint32_t aQ1 = st, aQ2 = st + P1_TILE;
        uint32_t bU1 = st + 2 * P1_TILE, bU2 = st + 3 * P1_TILE;
        uint32_t bG1 = st + 4 * P1_TILE, bG2 = st + 5 * P1_TILE;

#pragma unroll
        for (int s = 0; s < 4; s++) {           // 4 x k32 per chunk
            int kaB = s * 32 + colA;
            int kbB = s * 32 + colB;
            uint32_t A1f[2][4], A2f[2][4];
            ldmx4(A1f[0], aQ1 + SWZ(rowA * 128 + kaB));
            ldmx4(A1f[1], aQ1 + SWZ((rowA + 16) * 128 + kaB));
            ldmx4(A2f[0], aQ2 + SWZ(rowA * 128 + kaB));
            ldmx4(A2f[1], aQ2 + SWZ((rowA + 16) * 128 + kaB));
            uint32_t U1f[4], U2f[4], G1f[4], G2f[4];
            {
                uint32_t off = SWZ(rowB * 128 + kbB);
                ldmx4(U1f, bU1 + off);
                ldmx4(U2f, bU2 + off);
                ldmx4(G1f, bG1 + off);
                ldmx4(G2f, bG2 + off);
            }
            // term 1: a1*b1 -> d1
#pragma unroll
            for (int mi = 0; mi < 2; mi++)
#pragma unroll
                for (int nf = 0; nf < 2; nf++) {
                    imma16832(dU1[mi][nf], A1f[mi], U1f[nf * 2], U1f[nf * 2 + 1]);
                    imma16832(dG1[mi][nf], A1f[mi], G1f[nf * 2], G1f[nf * 2 + 1]);
                }
            // term 2: a1*b2 -> d2
#pragma unroll
            for (int mi = 0; mi < 2; mi++)
#pragma unroll
                for (int nf = 0; nf < 2; nf++) {
                    imma16832(dU2[mi][nf], A1f[mi], U2f[nf * 2], U2f[nf * 2 + 1]);
                    imma16832(dG2[mi][nf], A1f[mi], G2f[nf * 2], G2f[nf * 2 + 1]);
                }
            // term 3: a2*b1 -> d2
#pragma unroll
            for (int mi = 0; mi < 2; mi++)
#pragma unroll
                for (int nf = 0; nf < 2; nf++) {
                    imma16832(dU2[mi][nf], A2f[mi], U1f[nf * 2], U1f[nf * 2 + 1]);
                    imma16832(dG2[mi][nf], A2f[mi], G1f[nf * 2], G1f[nf * 2 + 1]);
                }
        }
        __syncthreads();
    }

    // ---- epilogue: dequant, h = w * silu(w*g) * (w*u), bf16 hi/lo ----
    int r4 = lane >> 2, c2 = (lane & 3) * 2;
#pragma unroll
    for (int mi = 0; mi < 2; mi++) {
#pragma unroll
        for (int half = 0; half < 2; half++) {
            int row = wm + mi * 16 + half * 8 + r4;
            int gm  = m0 + row;
            if (gm >= mEnd) continue;
            float w  = s_wt[row];
            float sa = s_sa[row];
#pragma unroll
            for (int nf = 0; nf < 2; nf++) {
                int colloc = wn + nf * 8 + c2;
                int col = n0 + colloc;
                float su0 = sa * s_su[colloc], su1 = sa * s_su[colloc + 1];
                float sg0 = sa * s_sg[colloc], sg1 = sa * s_sg[colloc + 1];
                int idx = half * 2;
                float u0 = w * su0 * ((float)dU1[mi][nf][idx]     + 0.0078125f * (float)dU2[mi][nf][idx]);
                float u1 = w * su1 * ((float)dU1[mi][nf][idx + 1] + 0.0078125f * (float)dU2[mi][nf][idx + 1]);
                float gg0 = w * sg0 * ((float)dG1[mi][nf][idx]     + 0.0078125f * (float)dG2[mi][nf][idx]);
                float gg1 = w * sg1 * ((float)dG1[mi][nf][idx + 1] + 0.0078125f * (float)dG2[mi][nf][idx + 1]);
                float r0 = w * (gg0 / (1.f + __expf(-gg0))) * u0;
                float r1 = w * (gg1 / (1.f + __expf(-gg1))) * u1;
                __nv_bfloat16 h0 = __float2bfloat16_rn(r0);
                __nv_bfloat16 h1 = __float2bfloat16_rn(r1);
                __nv_bfloat16 l0 = __float2bfloat16_rn(r0 - __bfloat162float(h0));
                __nv_bfloat16 l1 = __float2bfloat16_rn(r1 - __bfloat162float(h1));
                *(__nv_bfloat162*)&g_hhi[(size_t)gm * I_DIM + col] = __halves2bfloat162(h0, h1);
                *(__nv_bfloat162*)&g_hlo[(size_t)gm * I_DIM + col] = __halves2bfloat162(l0, l1);
            }
        }
    }
}

// ============================================================================
// pass2: grouped HMMA GEMM h @ w_down^T, CTA 128x64, K=512, bf16 3-term
// 2-stage, 2 CTAs/SM; hoisted cp.async addressing (unchanged from R7)
// ============================================================================
#define P2_ATILE 16384
#define P2_BTILE 8192
#define P2_STAGE (2 * P2_ATILE + 2 * P2_BTILE)  // 49152
#define P2_SMEM  (1024 + 2 * P2_STAGE)          // 99328
#define P2_NC    8

__global__ void __launch_bounds__(256, 2) pass2_mma() {
    int e     = blockIdx.z;
    int mBase = g_offsets[e];
    int mEnd  = g_offsets[e + 1];
    int m0    = mBase + blockIdx.y * 128;
    if (m0 >= mEnd) return;
    int n0 = blockIdx.x * 64;

    extern __shared__ char smem[];
    int* s_row  = (int*)smem;
    int* s_slot = (int*)(smem + 512);
    uint32_t tb = smem_u32(smem + 1024);

    int tid = threadIdx.x, wid = tid >> 5, lane = tid & 31;
    for (int r = tid; r < 128; r += 256) {
        int gm = m0 + r;
        s_row[r]  = (gm < mEnd) ? gm : mBase;
        s_slot[r] = (gm < mEnd) ? g_slot[gm] : 0;
    }
    __syncthreads();

    // hoisted load state
    int rowA2 = tid >> 1;
    int qa    = (tid & 1) * 4;
    uint32_t rbA = (uint32_t)rowA2 * 128;
    uint32_t cA  = (rbA >> 3) & 0x70;
    uint32_t dA[4];
#pragma unroll
    for (int j = 0; j < 4; j++) dA[j] = rbA + (((uint32_t)(qa + j) * 16) ^ cA);
    size_t aoff = (size_t)s_row[rowA2] * I_DIM + qa * 8;
    const __nv_bfloat16* sAh = g_hhi + aoff;
    const __nv_bfloat16* sAl = g_hlo + aoff;
    int rowB2 = tid >> 2;
    int qb    = (tid & 3) * 2;
    uint32_t rbB = (uint32_t)rowB2 * 128;
    uint32_t cB  = (rbB >> 3) & 0x70;
    uint32_t dB0 = rbB + (((uint32_t)qb * 16) ^ cB);
    uint32_t dB1 = rbB + (((uint32_t)(qb * 16 + 16)) ^ cB);
    size_t boff = ((size_t)e * H_DIM + n0 + rowB2) * I_DIM + qb * 8;
    const __nv_bfloat16* sBh = g_wd_hi + boff;
    const __nv_bfloat16* sBl = g_wd_lo + boff;

    float acc[2][4][4];
#pragma unroll
    for (int a = 0; a < 2; a++)
#pragma unroll
        for (int b = 0; b < 4; b++)
#pragma unroll
            for (int c = 0; c < 4; c++) acc[a][b][c] = 0.f;

    int wm = (wid >> 1) * 32;
    int wn = (wid & 1) * 32;
    int lgrp = lane >> 3, lr = lane & 7;
    int rowA = wm + (lgrp & 1) * 8 + lr;
    int rowB = wn + (lgrp >> 1) * 8 + lr;

    {
        uint32_t sb_ = tb;
#pragma unroll
        for (int j = 0; j < 4; j++) {
            cp_async16(sb_ + dA[j], sAh + j * 8);
            cp_async16(sb_ + P2_ATILE + dA[j], sAl + j * 8);
        }
        cp_async16(sb_ + 2 * P2_ATILE + dB0, sBh);
        cp_async16(sb_ + 2 * P2_ATILE + dB1, sBh + 8);
        cp_async16(sb_ + 2 * P2_ATILE + P2_BTILE + dB0, sBl);
        cp_async16(sb_ + 2 * P2_ATILE + P2_BTILE + dB1, sBl + 8);
        asm volatile("cp.async.commit_group;" ::: "memory");
    }

    for (int c = 0; c < P2_NC; c++) {
        if (c + 1 < P2_NC) {
            int k0 = (c + 1) * 64;
            uint32_t sb_ = tb + ((c + 1) & 1) * P2_STAGE;
#pragma unroll
            for (int j = 0; j < 4; j++) {
                cp_async16(sb_ + dA[j], sAh + k0 + j * 8);
                cp_async16(sb_ + P2_ATILE + dA[j], sAl + k0 + j * 8);
            }
            cp_async16(sb_ + 2 * P2_ATILE + dB0, sBh + k0);
            cp_async16(sb_ + 2 * P2_ATILE + dB1, sBh + k0 + 8);
            cp_async16(sb_ + 2 * P2_ATILE + P2_BTILE + dB0, sBl + k0);
            cp_async16(sb_ + 2 * P2_ATILE + P2_BTILE + dB1, sBl + k0 + 8);
            asm volatile("cp.async.commit_group;" ::: "memory");
            asm volatile("cp.async.wait_group 1;" ::: "memory");
        } else {
            asm volatile("cp.async.wait_group 0;" ::: "memory");
        }
        __syncthreads();

        uint32_t st  = tb + (c & 1) * P2_STAGE;
        uint32_t aHi = st, aLo = st + P2_ATILE;
        uint32_t bHi = st + 2 * P2_ATILE, bLo = bHi + P2_BTILE;

#pragma unroll
        for (int s = 0; s < 4; s++) {
            int kaB = (s * 16 + (lgrp >> 1) * 8) * 2;
            int kbB = (s * 16 + (lgrp & 1) * 8) * 2;
            uint32_t Ah[2][4], Al[2][4];
            ldmx4(Ah[0], aHi + SWZ(rowA * 128 + kaB));
            ldmx4(Ah[1], aHi + SWZ((rowA + 16) * 128 + kaB));
            ldmx4(Al[0], aLo + SWZ(rowA * 128 + kaB));
            ldmx4(Al[1], aLo + SWZ((rowA + 16) * 128 + kaB));
            uint32_t Bh[2][4], Bl[2][4];
#pragma unroll
            for (int p = 0; p < 2; p++) {
                uint32_t off = SWZ((rowB + p * 16) * 128 + kbB);
                ldmx4(Bh[p], bHi + off);
                ldmx4(Bl[p], bLo + off);
            }
#pragma unroll
            for (int mi = 0; mi < 2; mi++)
#pragma unroll
                for (int nf = 0; nf < 4; nf++) {
                    int p = nf >> 1, h = (nf & 1) * 2;
                    mma16816(acc[mi][nf], Ah[mi], Bh[p][h], Bh[p][h + 1]);
                }
#pragma unroll
            for (int mi = 0; mi < 2; mi++)
#pragma unroll
                for (int nf = 0; nf < 4; nf++) {
                    int p = nf >> 1, h = (nf & 1) * 2;
                    mma16816(acc[mi][nf], Al[mi], Bh[p][h], Bh[p][h + 1]);
                }
#pragma unroll
            for (int mi = 0; mi < 2; mi++)
#pragma unroll
                for (int nf = 0; nf < 4; nf++) {
                    int p = nf >> 1, h = (nf & 1) * 2;
                    mma16816(acc[mi][nf], Ah[mi], Bl[p][h], Bl[p][h + 1]);
                }
        }
        __syncthreads();
    }

    int r4 = lane >> 2, c2 = (lane & 3) * 2;
#pragma unroll
    for (int mi = 0; mi < 2; mi++) {
#pragma unroll
        for (int half = 0; half < 2; half++) {
            int row = wm + mi * 16 + half * 8 + r4;
            int gm  = m0 + row;
            if (gm >= mEnd) continue;
            int slot = s_slot[row];
#pragma unroll
            for (int nf = 0; nf < 4; nf++) {
                int col = n0 + wn + nf * 8 + c2;
                float2 v = make_float2(acc[mi][nf][half * 2 + 0], acc[mi][nf][half * 2 + 1]);
                *(float2*)&g_part[(size_t)slot * H_DIM + col] = v;
            }
        }
    }
}

// ---------------- reduce ----------------
__global__ void reduce_kernel(float* __restrict__ out) {
    int i = blockIdx.x * blockDim.x + threadIdx.x;
    int total = T_TOK * H_DIM / 4;
    if (i >= total) return;
    int t  = i / (H_DIM / 4);
    int hc = (i % (H_DIM / 4)) * 4;
    float4 s = make_float4(0.f, 0.f, 0.f, 0.f);
#pragma unroll
    for (int k = 0; k < TK; k++) {
        float4 v = *(const float4*)&g_part[(size_t)(t * TK + k) * H_DIM + hc];
        s.x += v.x; s.y += v.y; s.z += v.z; s.w += v.w;
    }
    *(float4*)&out[(size_t)t * H_DIM + hc] = s;
}

// ---------------- launch ----------------
extern "C" void kernel_launch(void* const* d_in, const int* in_sizes, int n_in,
                              void* d_out, int out_size)
{
    const float* x             = (const float*)d_in[0];
    const float* router_logits = (const float*)d_in[1];
    const float* w_up          = (const float*)d_in[2];
    const float* w_gate        = (const float*)d_in[3];
    const float* w_down        = (const float*)d_in[4];
    float* out = (float*)d_out;

    cudaFuncSetAttribute(pass1_mma, cudaFuncAttributeMaxDynamicSharedMemorySize, P1_SMEM);
    cudaFuncSetAttribute(pass2_mma, cudaFuncAttributeMaxDynamicSharedMemorySize, P2_SMEM);

    // #1 routing, #2 conv_int8, #3 conv_wd, #4 pass1 (profiled), #5 pass2, #6 reduce
    routing_kernel<<<1, 1024>>>(router_logits);
    conv_int8_kernel<<<CONV8_ROWS, 128>>>(x, w_up, w_gate);
    conv_wd_kernel<<<(NWD4 + 255) / 256, 256>>>((const float4*)w_down);

    dim3 g1(I_DIM / 64, T_TOK / 64, NE);
    pass1_mma<<<g1, 256, P1_SMEM>>>();

    dim3 g2(H_DIM / 64, T_TOK / 128, NE);
    pass2_mma<<<g2, 256, P2_SMEM>>>();

    reduce_kernel<<<(T_TOK * H_DIM / 4 + 255) / 256, 256>>>(out);
}

// round 10
// speedup vs baseline: 1.5944x; 1.1986x over previous
#include <cuda_runtime.h>
#include <cuda_bf16.h>
#include <math.h>
#include <stdint.h>

// Problem constants
#define T_TOK 2048
#define H_DIM 1024
#define I_DIM 512
#define NE    16
#define TK    4
#define NPAIR (T_TOK * TK)   // 8192

// ---------------- scratch (device globals; no allocation) ----------------
__device__ int   g_offsets[NE + 1];
__device__ int   g_ids[NPAIR];
__device__ float g_wt[NPAIR];
__device__ int   g_slot[NPAIR];

// int8 two-level quantized pass1 inputs + per-row scales
__device__ __align__(16) signed char g_x1[T_TOK * H_DIM];
__device__ __align__(16) signed char g_x2[T_TOK * H_DIM];
__device__ __align__(16) signed char g_u1[NE * I_DIM * H_DIM];
__device__ __align__(16) signed char g_u2[NE * I_DIM * H_DIM];
__device__ __align__(16) signed char g_g1[NE * I_DIM * H_DIM];
__device__ __align__(16) signed char g_g2[NE * I_DIM * H_DIM];
__device__ float g_sx[T_TOK];
__device__ float g_su[NE * I_DIM];
__device__ float g_sg[NE * I_DIM];

// pass2 operands: h fp32 (pass1 output) -> two-level int8; w_down two-level int8
__device__ __align__(16) float g_h[(size_t)NPAIR * I_DIM];        // 16.8 MB
__device__ __align__(16) signed char g_h1[(size_t)NPAIR * I_DIM];
__device__ __align__(16) signed char g_h2[(size_t)NPAIR * I_DIM];
__device__ float g_sh[NPAIR];
__device__ __align__(16) signed char g_wd1[NE * H_DIM * I_DIM];
__device__ __align__(16) signed char g_wd2[NE * H_DIM * I_DIM];
__device__ float g_swd[NE * H_DIM];

__device__ __align__(16) float g_part[(size_t)NPAIR * H_DIM];     // 32 MB

// ---------------- helpers ----------------
__device__ __forceinline__ uint32_t smem_u32(const void* p) {
    uint32_t a;
    asm("{ .reg .u64 t; cvta.to.shared.u64 t, %1; cvt.u32.u64 %0, t; }" : "=r"(a) : "l"(p));
    return a;
}
__device__ __forceinline__ void cp_async16(uint32_t dst, const void* src) {
    asm volatile("cp.async.cg.shared.global [%0], [%1], 16;" :: "r"(dst), "l"(src));
}
__device__ __forceinline__ void ldmx4(uint32_t r[4], uint32_t addr) {
    asm volatile("ldmatrix.sync.aligned.m8n8.x4.shared.b16 {%0,%1,%2,%3}, [%4];"
                 : "=r"(r[0]), "=r"(r[1]), "=r"(r[2]), "=r"(r[3]) : "r"(addr));
}
__device__ __forceinline__ void imma16832(int d[4], const uint32_t a[4], uint32_t b0, uint32_t b1) {
    asm("mma.sync.aligned.m16n8k32.row.col.s32.s8.s8.s32 "
        "{%0,%1,%2,%3}, {%4,%5,%6,%7}, {%8,%9}, {%0,%1,%2,%3};"
        : "+r"(d[0]), "+r"(d[1]), "+r"(d[2]), "+r"(d[3])
        : "r"(a[0]), "r"(a[1]), "r"(a[2]), "r"(a[3]), "r"(b0), "r"(b1));
}
#define SWZ(o) ((o) ^ (((o) >> 3) & 0x70))

// ---------------- kernel: fused routing (router + scan + scatter), 1 block ----------------
__global__ void __launch_bounds__(1024) routing_kernel(const float* __restrict__ logits) {
    __shared__ int s_cnt[NE], s_cur[NE], s_off[NE + 1];
    int tid = threadIdx.x;
    if (tid < NE) { s_cnt[tid] = 0; s_cur[tid] = 0; }
    __syncthreads();

    for (int t = tid; t < T_TOK; t += 1024) {
        float l[NE];
#pragma unroll
        for (int e = 0; e < NE; e++) l[e] = logits[t * NE + e];
        int ids[TK]; float vals[TK];
        unsigned mask = 0;
#pragma unroll
        for (int k = 0; k < TK; k++) {
            float best = -1e30f; int bi = 0;
#pragma unroll
            for (int e = 0; e < NE; e++)
                if (!((mask >> e) & 1u) && l[e] > best) { best = l[e]; bi = e; }
            ids[k] = bi; vals[k] = best; mask |= (1u << bi);
        }
        float m = vals[0];
        float w[TK]; float s = 0.f;
#pragma unroll
        for (int k = 0; k < TK; k++) { w[k] = expf(vals[k] - m); s += w[k]; }
        float inv = 1.f / s;
#pragma unroll
        for (int k = 0; k < TK; k++) {
            g_ids[t * TK + k] = ids[k];
            g_wt[t * TK + k]  = w[k] * inv;
            atomicAdd(&s_cnt[ids[k]], 1);
        }
    }
    __syncthreads();
    if (tid == 0) {
        int acc = 0;
        s_off[0] = 0; g_offsets[0] = 0;
#pragma unroll
        for (int e = 0; e < NE; e++) {
            acc += s_cnt[e];
            s_off[e + 1] = acc;
            g_offsets[e + 1] = acc;
        }
    }
    __syncthreads();
    for (int t = tid; t < T_TOK; t += 1024) {
#pragma unroll
        for (int k = 0; k < TK; k++) {
            int e = g_ids[t * TK + k];
            int pos = s_off[e] + atomicAdd(&s_cur[e], 1);
            g_slot[pos] = t * TK + k;
        }
    }
}

// ---------------- kernel: fp32 -> two-level int8 with per-row scale (len 1024) ----------------
// rows: [0,2048) -> x; [2048,10240) -> w_up; [10240,18432) -> w_gate
#define CONV8_ROWS (T_TOK + 2 * NE * I_DIM)
__global__ void __launch_bounds__(128) conv_int8_kernel(const float* __restrict__ x,
                                                        const float* __restrict__ wu,
                                                        const float* __restrict__ wg) {
    int r = blockIdx.x;
    const float* src; signed char* q1; signed char* q2; float* sc; int row;
    if (r < T_TOK)                 { src = x;  q1 = g_x1; q2 = g_x2; sc = g_sx; row = r; }
    else if (r < T_TOK + NE*I_DIM) { src = wu; q1 = g_u1; q2 = g_u2; sc = g_su; row = r - T_TOK; }
    else                           { src = wg; q1 = g_g1; q2 = g_g2; sc = g_sg; row = r - T_TOK - NE*I_DIM; }

    const float4* p4 = (const float4*)(src + (size_t)row * H_DIM + threadIdx.x * 8);
    float4 a = p4[0], b = p4[1];
    float v[8] = {a.x, a.y, a.z, a.w, b.x, b.y, b.z, b.w};
    float m = 0.f;
#pragma unroll
    for (int j = 0; j < 8; j++) m = fmaxf(m, fabsf(v[j]));
#pragma unroll
    for (int o = 16; o; o >>= 1) m = fmaxf(m, __shfl_xor_sync(0xFFFFFFFFu, m, o));
    __shared__ float sm[4];
    __shared__ float s_inv;
    if ((threadIdx.x & 31) == 0) sm[threadIdx.x >> 5] = m;
    __syncthreads();
    if (threadIdx.x == 0) {
        float mm = fmaxf(fmaxf(sm[0], sm[1]), fmaxf(sm[2], sm[3]));
        sc[row] = mm * (1.f / 127.f);
        s_inv   = (mm > 0.f) ? (127.f / mm) : 0.f;
    }
    __syncthreads();
    float inv = s_inv;
    unsigned long long u1 = 0, u2 = 0;
#pragma unroll
    for (int j = 0; j < 8; j++) {
        float t  = v[j] * inv;
        float t1 = rintf(t);
        int c1 = (int)t1;
        int c2 = (int)rintf((t - t1) * 128.f);
        u1 |= ((unsigned long long)(unsigned char)(signed char)c1) << (8 * j);
        u2 |= ((unsigned long long)(unsigned char)(signed char)c2) << (8 * j);
    }
    size_t o = (size_t)row * H_DIM + threadIdx.x * 8;
    *(unsigned long long*)(q1 + o) = u1;
    *(unsigned long long*)(q2 + o) = u2;
}

// ---------------- two-level quant for rows of length 512 (64 threads/block) ----------------
__device__ __forceinline__ void quant_row512(const float* __restrict__ srcrow,
                                             signed char* __restrict__ q1,
                                             signed char* __restrict__ q2,
                                             float* __restrict__ sc, int row) {
    int tid = threadIdx.x;   // 0..63
    const float4* p4 = (const float4*)(srcrow + tid * 8);
    float4 a = p4[0], b = p4[1];
    float v[8] = {a.x, a.y, a.z, a.w, b.x, b.y, b.z, b.w};
    float m = 0.f;
#pragma unroll
    for (int j = 0; j < 8; j++) m = fmaxf(m, fabsf(v[j]));
#pragma unroll
    for (int o = 16; o; o >>= 1) m = fmaxf(m, __shfl_xor_sync(0xFFFFFFFFu, m, o));
    __shared__ float sm[2];
    __shared__ float s_inv;
    if ((tid & 31) == 0) sm[tid >> 5] = m;
    __syncthreads();
    if (tid == 0) {
        float mm = fmaxf(sm[0], sm[1]);
        sc[row] = mm * (1.f / 127.f);
        s_inv   = (mm > 0.f) ? (127.f / mm) : 0.f;
    }
    __syncthreads();
    float inv = s_inv;
    unsigned long long u1 = 0, u2 = 0;
#pragma unroll
    for (int j = 0; j < 8; j++) {
        float t  = v[j] * inv;
        float t1 = rintf(t);
        int c1 = (int)t1;
        int c2 = (int)rintf((t - t1) * 128.f);
        u1 |= ((unsigned long long)(unsigned char)(signed char)c1) << (8 * j);
        u2 |= ((unsigned long long)(unsigned char)(signed char)c2) << (8 * j);
    }
    size_t o = (size_t)row * I_DIM + tid * 8;
    *(unsigned long long*)(q1 + o) = u1;
    *(unsigned long long*)(q2 + o) = u2;
}

__global__ void __launch_bounds__(64) conv_wd8_kernel(const float* __restrict__ wd) {
    int row = blockIdx.x;                 // NE*H_DIM rows
    quant_row512(wd + (size_t)row * I_DIM, g_wd1, g_wd2, g_swd, row);
}
__global__ void __launch_bounds__(64) quant_h_kernel() {
    int row = blockIdx.x;                 // NPAIR rows
    quant_row512(g_h + (size_t)row * I_DIM, g_h1, g_h2, g_sh, row);
}

// ============================================================================
// pass1: grouped int8 IMMA GEMM, CTA 64x64, K=1024, fused up+gate,
// two-level int8 (3-term). Epilogue now writes h as fp32.
// ============================================================================
#define P1_TILE  8192                           // 64 rows x 128B
#define P1_STAGE (6 * P1_TILE)                  // A1,A2,U1,U2,G1,G2 = 48KB
#define P1_SMEM  (2048 + 2 * P1_STAGE)          // 100352 -> 2 CTAs/SM
#define P1_NC    8                              // 1024 / 128

__global__ void __launch_bounds__(256, 2) pass1_mma() {
    int e     = blockIdx.z;
    int mBase = g_offsets[e];
    int mEnd  = g_offsets[e + 1];
    int m0    = mBase + blockIdx.y * 64;
    if (m0 >= mEnd) return;
    int n0 = blockIdx.x * 64;

    extern __shared__ char smem[];
    int*   s_tok = (int*)smem;             // 64
    float* s_wt  = (float*)(smem + 256);   // 64
    float* s_sa  = (float*)(smem + 512);   // 64  A row scales
    float* s_su  = (float*)(smem + 768);   // 64  up col scales
    float* s_sg  = (float*)(smem + 1024);  // 64  gate col scales
    uint32_t tb  = smem_u32(smem + 2048);

    int tid = threadIdx.x, wid = tid >> 5, lane = tid & 31;
    for (int r = tid; r < 64; r += 256) {
        int gm = m0 + r;
        int slot = (gm < mEnd) ? g_slot[gm] : g_slot[mBase];
        int tok = slot >> 2;
        s_tok[r] = tok;
        s_wt[r]  = g_wt[slot];
        s_sa[r]  = g_sx[tok];
        s_su[r]  = g_su[e * I_DIM + n0 + r];
        s_sg[r]  = g_sg[e * I_DIM + n0 + r];
    }
    __syncthreads();

    // hoisted per-thread load state
    int lrow = tid >> 2;            // 0..63
    int qp   = tid & 3;             // 32B slice
    uint32_t rbase = (uint32_t)lrow * 128;
    uint32_t cswz  = (rbase >> 3) & 0x70;
    uint32_t d0 = rbase + (((uint32_t)(qp * 32)) ^ cswz);
    uint32_t d1 = rbase + (((uint32_t)(qp * 32 + 16)) ^ cswz);
    size_t aoff = (size_t)s_tok[lrow] * H_DIM + qp * 32;
    size_t boff = ((size_t)e * I_DIM + n0 + lrow) * H_DIM + qp * 32;
    const signed char* sA1 = g_x1 + aoff;
    const signed char* sA2 = g_x2 + aoff;
    const signed char* sU1 = g_u1 + boff;
    const signed char* sU2 = g_u2 + boff;
    const signed char* sG1 = g_g1 + boff;
    const signed char* sG2 = g_g2 + boff;

    int dU1[2][2][4], dU2[2][2][4], dG1[2][2][4], dG2[2][2][4];
#pragma unroll
    for (int a = 0; a < 2; a++)
#pragma unroll
        for (int b = 0; b < 2; b++)
#pragma unroll
            for (int c = 0; c < 4; c++) {
                dU1[a][b][c] = 0; dU2[a][b][c] = 0;
                dG1[a][b][c] = 0; dG2[a][b][c] = 0;
            }

    int wm = (wid >> 2) * 32;
    int wn = (wid & 3) * 16;
    int lgrp = lane >> 3, lr = lane & 7;
    int rowA = wm + (lgrp & 1) * 8 + lr;
    int rowB = wn + (lgrp >> 1) * 8 + lr;
    int colA = (lgrp >> 1) * 16;
    int colB = (lgrp & 1) * 16;

    {
        uint32_t sb_ = tb;
        cp_async16(sb_ + d0, sA1);                   cp_async16(sb_ + d1, sA1 + 16);
        cp_async16(sb_ + P1_TILE + d0, sA2);         cp_async16(sb_ + P1_TILE + d1, sA2 + 16);
        cp_async16(sb_ + 2 * P1_TILE + d0, sU1);     cp_async16(sb_ + 2 * P1_TILE + d1, sU1 + 16);
        cp_async16(sb_ + 3 * P1_TILE + d0, sU2);     cp_async16(sb_ + 3 * P1_TILE + d1, sU2 + 16);
        cp_async16(sb_ + 4 * P1_TILE + d0, sG1);     cp_async16(sb_ + 4 * P1_TILE + d1, sG1 + 16);
        cp_async16(sb_ + 5 * P1_TILE + d0, sG2);     cp_async16(sb_ + 5 * P1_TILE + d1, sG2 + 16);
        asm volatile("cp.async.commit_group;" ::: "memory");
    }

    for (int c = 0; c < P1_NC; c++) {
        if (c + 1 < P1_NC) {
            int k0 = (c + 1) * 128;
            uint32_t sb_ = tb + ((c + 1) & 1) * P1_STAGE;
            cp_async16(sb_ + d0, sA1 + k0);                cp_async16(sb_ + d1, sA1 + k0 + 16);
            cp_async16(sb_ + P1_TILE + d0, sA2 + k0);      cp_async16(sb_ + P1_TILE + d1, sA2 + k0 + 16);
            cp_async16(sb_ + 2 * P1_TILE + d0, sU1 + k0);  cp_async16(sb_ + 2 * P1_TILE + d1, sU1 + k0 + 16);
            cp_async16(sb_ + 3 * P1_TILE + d0, sU2 + k0);  cp_async16(sb_ + 3 * P1_TILE + d1, sU2 + k0 + 16);
            cp_async16(sb_ + 4 * P1_TILE + d0, sG1 + k0);  cp_async16(sb_ + 4 * P1_TILE + d1, sG1 + k0 + 16);
            cp_async16(sb_ + 5 * P1_TILE + d0, sG2 + k0);  cp_async16(sb_ + 5 * P1_TILE + d1, sG2 + k0 + 16);
            asm volatile("cp.async.commit_group;" ::: "memory");
            asm volatile("cp.async.wait_group 1;" ::: "memory");
        } else {
            asm volatile("cp.async.wait_group 0;" ::: "memory");
        }
        __syncthreads();

        uint32_t st = tb + (c & 1) * P1_STAGE;
        uint32_t aQ1 = st, aQ2 = st + P1_TILE;
        uint32_t bU1 = st + 2 * P1_TILE, bU2 = st + 3 * P1_TILE;
        uint32_t bG1 = st + 4 * P1_TILE, bG2 = st + 5 * P1_TILE;

#pragma unroll
        for (int s = 0; s < 4; s++) {
            int kaB = s * 32 + colA;
            int kbB = s * 32 + colB;
            uint32_t A1f[2][4], A2f[2][4];
            ldmx4(A1f[0], aQ1 + SWZ(rowA * 128 + kaB));
            ldmx4(A1f[1], aQ1 + SWZ((rowA + 16) * 128 + kaB));
            ldmx4(A2f[0], aQ2 + SWZ(rowA * 128 + kaB));
            ldmx4(A2f[1], aQ2 + SWZ((rowA + 16) * 128 + kaB));
            uint32_t U1f[4], U2f[4], G1f[4], G2f[4];
            {
                uint32_t off = SWZ(rowB * 128 + kbB);
                ldmx4(U1f, bU1 + off);
                ldmx4(U2f, bU2 + off);
                ldmx4(G1f, bG1 + off);
                ldmx4(G2f, bG2 + off);
            }
#pragma unroll
            for (int mi = 0; mi < 2; mi++)
#pragma unroll
                for (int nf = 0; nf < 2; nf++) {
                    imma16832(dU1[mi][nf], A1f[mi], U1f[nf * 2], U1f[nf * 2 + 1]);
                    imma16832(dG1[mi][nf], A1f[mi], G1f[nf * 2], G1f[nf * 2 + 1]);
                }
#pragma unroll
            for (int mi = 0; mi < 2; mi++)
#pragma unroll
                for (int nf = 0; nf < 2; nf++) {
                    imma16832(dU2[mi][nf], A1f[mi], U2f[nf * 2], U2f[nf * 2 + 1]);
                    imma16832(dG2[mi][nf], A1f[mi], G2f[nf * 2], G2f[nf * 2 + 1]);
                }
#pragma unroll
            for (int mi = 0; mi < 2; mi++)
#pragma unroll
                for (int nf = 0; nf < 2; nf++) {
                    imma16832(dU2[mi][nf], A2f[mi], U1f[nf * 2], U1f[nf * 2 + 1]);
                    imma16832(dG2[mi][nf], A2f[mi], G1f[nf * 2], G1f[nf * 2 + 1]);
                }
        }
        __syncthreads();
    }

    // ---- epilogue: dequant, h = w * silu(w*g) * (w*u), store fp32 ----
    int r4 = lane >> 2, c2 = (lane & 3) * 2;
#pragma unroll
    for (int mi = 0; mi < 2; mi++) {
#pragma unroll
        for (int half = 0; half < 2; half++) {
            int row = wm + mi * 16 + half * 8 + r4;
            int gm  = m0 + row;
            if (gm >= mEnd) continue;
            float w  = s_wt[row];
            float sa = s_sa[row];
#pragma unroll
            for (int nf = 0; nf < 2; nf++) {
                int colloc = wn + nf * 8 + c2;
                int col = n0 + colloc;
                float su0 = sa * s_su[colloc], su1 = sa * s_su[colloc + 1];
                float sg0 = sa * s_sg[colloc], sg1 = sa * s_sg[colloc + 1];
                int idx = half * 2;
                float u0 = w * su0 * ((float)dU1[mi][nf][idx]     + 0.0078125f * (float)dU2[mi][nf][idx]);
                float u1 = w * su1 * ((float)dU1[mi][nf][idx + 1] + 0.0078125f * (float)dU2[mi][nf][idx + 1]);
                float gg0 = w * sg0 * ((float)dG1[mi][nf][idx]     + 0.0078125f * (float)dG2[mi][nf][idx]);
                float gg1 = w * sg1 * ((float)dG1[mi][nf][idx + 1] + 0.0078125f * (float)dG2[mi][nf][idx + 1]);
                float r0 = w * (gg0 / (1.f + __expf(-gg0))) * u0;
                float r1 = w * (gg1 / (1.f + __expf(-gg1))) * u1;
                *(float2*)&g_h[(size_t)gm * I_DIM + col] = make_float2(r0, r1);
            }
        }
    }
}

// ============================================================================
// pass2: grouped int8 IMMA GEMM h @ w_down^T, CTA 128x64, K=512, two-level int8
// 4 chunks of 128B; 2-stage, 2 CTAs/SM.
// ============================================================================
#define P2_TILE_A 16384                          // 128 rows x 128B
#define P2_TILE_B 8192                           // 64 rows x 128B
#define P2_STAGE  (2 * P2_TILE_A + 2 * P2_TILE_B)  // 49152
#define P2_SMEM   (2048 + 2 * P2_STAGE)            // 100352
#define P2_NC     4                                // 512 / 128

__global__ void __launch_bounds__(256, 2) pass2_mma() {
    int e     = blockIdx.z;
    int mBase = g_offsets[e];
    int mEnd  = g_offsets[e + 1];
    int m0    = mBase + blockIdx.y * 128;
    if (m0 >= mEnd) return;
    int n0 = blockIdx.x * 64;

    extern __shared__ char smem[];
    int*   s_row  = (int*)smem;             // 128
    int*   s_slot = (int*)(smem + 512);     // 128
    float* s_sa   = (float*)(smem + 1024);  // 128  h row scales
    float* s_sb   = (float*)(smem + 1536);  // 64   w_down col scales
    uint32_t tb = smem_u32(smem + 2048);

    int tid = threadIdx.x, wid = tid >> 5, lane = tid & 31;
    for (int r = tid; r < 128; r += 256) {
        int gm = m0 + r;
        int rr = (gm < mEnd) ? gm : mBase;
        s_row[r]  = rr;
        s_slot[r] = (gm < mEnd) ? g_slot[gm] : 0;
        s_sa[r]   = g_sh[rr];
    }
    for (int r = tid; r < 64; r += 256)
        s_sb[r] = g_swd[e * H_DIM + n0 + r];
    __syncthreads();

    // hoisted load state: A 128 rows, 2 threads/row, 64B each
    int rowA2 = tid >> 1;
    int qa    = (tid & 1) * 4;           // 16B quads
    uint32_t rbA = (uint32_t)rowA2 * 128;
    uint32_t cA  = (rbA >> 3) & 0x70;
    uint32_t dA[4];
#pragma unroll
    for (int j = 0; j < 4; j++) dA[j] = rbA + (((uint32_t)(qa + j) * 16) ^ cA);
    size_t aoff = (size_t)s_row[rowA2] * I_DIM + qa * 16;
    const signed char* sA1 = g_h1 + aoff;
    const signed char* sA2 = g_h2 + aoff;
    // B 64 rows, 4 threads/row, 32B each
    int rowB2 = tid >> 2;
    int qb    = tid & 3;
    uint32_t rbB = (uint32_t)rowB2 * 128;
    uint32_t cB  = (rbB >> 3) & 0x70;
    uint32_t dB0 = rbB + (((uint32_t)(qb * 32)) ^ cB);
    uint32_t dB1 = rbB + (((uint32_t)(qb * 32 + 16)) ^ cB);
    size_t boff = ((size_t)e * H_DIM + n0 + rowB2) * I_DIM + qb * 32;
    const signed char* sB1 = g_wd1 + boff;
    const signed char* sB2 = g_wd2 + boff;

    int d1[2][4][4], d2[2][4][4];
#pragma unroll
    for (int a = 0; a < 2; a++)
#pragma unroll
        for (int b = 0; b < 4; b++)
#pragma unroll
            for (int c = 0; c < 4; c++) { d1[a][b][c] = 0; d2[a][b][c] = 0; }

    int wm = (wid >> 1) * 32;
    int wn = (wid & 1) * 32;
    int lgrp = lane >> 3, lr = lane & 7;
    int rowA = wm + (lgrp & 1) * 8 + lr;
    int rowB = wn + (lgrp >> 1) * 8 + lr;
    int colA = (lgrp >> 1) * 16;
    int colB = (lgrp & 1) * 16;

    {
        uint32_t sb_ = tb;
#pragma unroll
        for (int j = 0; j < 4; j++) {
            cp_async16(sb_ + dA[j], sA1 + j * 16);
            cp_async16(sb_ + P2_TILE_A + dA[j], sA2 + j * 16);
        }
        cp_async16(sb_ + 2 * P2_TILE_A + dB0, sB1);
        cp_async16(sb_ + 2 * P2_TILE_A + dB1, sB1 + 16);
        cp_async16(sb_ + 2 * P2_TILE_A + P2_TILE_B + dB0, sB2);
        cp_async16(sb_ + 2 * P2_TILE_A + P2_TILE_B + dB1, sB2 + 16);
        asm volatile("cp.async.commit_group;" ::: "memory");
    }

    for (int c = 0; c < P2_NC; c++) {
        if (c + 1 < P2_NC) {
            int k0 = (c + 1) * 128;
            uint32_t sb_ = tb + ((c + 1) & 1) * P2_STAGE;
#pragma unroll
            for (int j = 0; j < 4; j++) {
                cp_async16(sb_ + dA[j], sA1 + k0 + j * 16);
                cp_async16(sb_ + P2_TILE_A + dA[j], sA2 + k0 + j * 16);
            }
            cp_async16(sb_ + 2 * P2_TILE_A + dB0, sB1 + k0);
            cp_async16(sb_ + 2 * P2_TILE_A + dB1, sB1 + k0 + 16);
            cp_async16(sb_ + 2 * P2_TILE_A + P2_TILE_B + dB0, sB2 + k0);
            cp_async16(sb_ + 2 * P2_TILE_A + P2_TILE_B + dB1, sB2 + k0 + 16);
            asm volatile("cp.async.commit_group;" ::: "memory");
            asm volatile("cp.async.wait_group 1;" ::: "memory");
        } else {
            asm volatile("cp.async.wait_group 0;" ::: "memory");
        }
        __syncthreads();

        uint32_t st = tb + (c & 1) * P2_STAGE;
        uint32_t a1 = st, a2 = st + P2_TILE_A;
        uint32_t b1 = st + 2 * P2_TILE_A, b2 = b1 + P2_TILE_B;

#pragma unroll
        for (int s = 0; s < 4; s++) {
            int kaB = s * 32 + colA;
            int kbB = s * 32 + colB;
            uint32_t A1f[2][4], A2f[2][4];
            ldmx4(A1f[0], a1 + SWZ(rowA * 128 + kaB));
            ldmx4(A1f[1], a1 + SWZ((rowA + 16) * 128 + kaB));
            ldmx4(A2f[0], a2 + SWZ(rowA * 128 + kaB));
            ldmx4(A2f[1], a2 + SWZ((rowA + 16) * 128 + kaB));
            uint32_t B1f[2][4], B2f[2][4];
#pragma unroll
            for (int p = 0; p < 2; p++) {
                uint32_t off = SWZ((rowB + p * 16) * 128 + kbB);
                ldmx4(B1f[p], b1 + off);
                ldmx4(B2f[p], b2 + off);
            }
            // term 1: a1*b1 -> d1
#pragma unroll
            for (int mi = 0; mi < 2; mi++)
#pragma unroll
                for (int nf = 0; nf < 4; nf++) {
                    int p = nf >> 1, h = (nf & 1) * 2;
                    imma16832(d1[mi][nf], A1f[mi], B1f[p][h], B1f[p][h + 1]);
                }
            // term 2: a1*b2 -> d2
#pragma unroll
            for (int mi = 0; mi < 2; mi++)
#pragma unroll
                for (int nf = 0; nf < 4; nf++) {
                    int p = nf >> 1, h = (nf & 1) * 2;
                    imma16832(d2[mi][nf], A1f[mi], B2f[p][h], B2f[p][h + 1]);
                }
            // term 3: a2*b1 -> d2
#pragma unroll
            for (int mi = 0; mi < 2; mi++)
#pragma unroll
                for (int nf = 0; nf < 4; nf++) {
                    int p = nf >> 1, h = (nf & 1) * 2;
                    imma16832(d2[mi][nf], A2f[mi], B1f[p][h], B1f[p][h + 1]);
                }
        }
        __syncthreads();
    }

    int r4 = lane >> 2, c2 = (lane & 3) * 2;
#pragma unroll
    for (int mi = 0; mi < 2; mi++) {
#pragma unroll
        for (int half = 0; half < 2; half++) {
            int row = wm + mi * 16 + half * 8 + r4;
            int gm  = m0 + row;
            if (gm >= mEnd) continue;
            int slot = s_slot[row];
            float sa = s_sa[row];
#pragma unroll
            for (int nf = 0; nf < 4; nf++) {
                int colloc = wn + nf * 8 + c2;
                int col = n0 + colloc;
                float sb0 = sa * s_sb[colloc];
                float sb1 = sa * s_sb[colloc + 1];
                int idx = half * 2;
                float v0 = sb0 * ((float)d1[mi][nf][idx]     + 0.0078125f * (float)d2[mi][nf][idx]);
                float v1 = sb1 * ((float)d1[mi][nf][idx + 1] + 0.0078125f * (float)d2[mi][nf][idx + 1]);
                *(float2*)&g_part[(size_t)slot * H_DIM + col] = make_float2(v0, v1);
            }
        }
    }
}

// ---------------- reduce ----------------
__global__ void reduce_kernel(float* __restrict__ out) {
    int i = blockIdx.x * blockDim.x + threadIdx.x;
    int total = T_TOK * H_DIM / 4;
    if (i >= total) return;
    int t  = i / (H_DIM / 4);
    int hc = (i % (H_DIM / 4)) * 4;
    float4 s = make_float4(0.f, 0.f, 0.f, 0.f);
#pragma unroll
    for (int k = 0; k < TK; k++) {
        float4 v = *(const float4*)&g_part[(size_t)(t * TK + k) * H_DIM + hc];
        s.x += v.x; s.y += v.y; s.z += v.z; s.w += v.w;
    }
    *(float4*)&out[(size_t)t * H_DIM + hc] = s;
}

// ---------------- launch ----------------
extern "C" void kernel_launch(void* const* d_in, const int* in_sizes, int n_in,
                              void* d_out, int out_size)
{
    const float* x             = (const float*)d_in[0];
    const float* router_logits = (const float*)d_in[1];
    const float* w_up          = (const float*)d_in[2];
    const float* w_gate        = (const float*)d_in[3];
    const float* w_down        = (const float*)d_in[4];
    float* out = (float*)d_out;

    cudaFuncSetAttribute(pass1_mma, cudaFuncAttributeMaxDynamicSharedMemorySize, P1_SMEM);
    cudaFuncSetAttribute(pass2_mma, cudaFuncAttributeMaxDynamicSharedMemorySize, P2_SMEM);

    // #1 routing, #2 conv_int8, #3 conv_wd8, #4 pass1 (profiled), #5 quant_h, #6 pass2, #7 reduce
    routing_kernel<<<1, 1024>>>(router_logits);
    conv_int8_kernel<<<CONV8_ROWS, 128>>>(x, w_up, w_gate);
    conv_wd8_kernel<<<NE * H_DIM, 64>>>(w_down);

    dim3 g1(I_DIM / 64, T_TOK / 64, NE);
    pass1_mma<<<g1, 256, P1_SMEM>>>();

    quant_h_kernel<<<NPAIR, 64>>>();

    dim3 g2(H_DIM / 64, T_TOK / 128, NE);
    pass2_mma<<<g2, 256, P2_SMEM>>>();

    reduce_kernel<<<(T_TOK * H_DIM / 4 + 255) / 256, 256>>>(out);
}